// round 2
// baseline (speedup 1.0000x reference)
#include <cuda_runtime.h>
#include <cuda_bf16.h>
#include <math.h>

#define BN 4
#define HH 192
#define WW 192
#define PP (HH*WW)           // 36864
#define CF 64
#define ONC 64
#define INC 7
#define PTILES (PP/128)      // 288

// ---------------- scratch (device globals; no runtime allocation) ----------------
__device__ float g_dw[BN * CF * PP];            // depthwise output
__device__ float g_om[BN * 525 * PP];           // offset/mask (max k=5)
__device__ float g_stack[BN * 3 * ONC * PP];    // stacked branch outputs
__device__ float g_attp[BN * ONC * PTILES];     // attn partial sums
__device__ float g_att[BN * ONC];
__device__ float g_atts[BN * 3 * ONC];
__device__ float g_Wb[BN * ONC * 3 * ONC];      // per-batch scaled conv_w

// ---------------- depthwise conv (k = 1,3,5, SAME padding), 4 px / thread ----------------
template <int KK>
__global__ void dw_conv_kernel(const float* __restrict__ x,
                               const float* __restrict__ w,
                               const float* __restrict__ bias,
                               float* __restrict__ y)
{
    const int P4 = PP / 4;
    int idx = blockIdx.x * blockDim.x + threadIdx.x;
    if (idx >= BN * CF * P4) return;
    int p4 = idx % P4;
    int c  = (idx / P4) % CF;
    int b  = idx / (CF * P4);
    int p  = p4 * 4;
    int h  = p / WW;
    int x0 = p - h * WW;                 // WW divisible by 4: 4 px same row
    const int pad = KK / 2;
    const float* xp = x + ((long)(b * CF + c)) * PP;
    const float* wp = w + c * KK * KK;

    float acc[4];
    float bb = bias[c];
#pragma unroll
    for (int i = 0; i < 4; i++) acc[i] = bb;

    bool inter = (h >= pad) && (h < HH - pad) && (x0 >= pad) && (x0 + 3 + pad < WW);

#pragma unroll
    for (int ky = 0; ky < KK; ky++) {
        int yy = h + ky - pad;
        const float* r = xp + yy * WW + x0 - pad;
        float v[KK + 3];
        if (inter) {
#pragma unroll
            for (int m = 0; m < KK + 3; m++) v[m] = r[m];
        } else {
            bool vy = (yy >= 0) && (yy < HH);
#pragma unroll
            for (int m = 0; m < KK + 3; m++) {
                int xx = x0 - pad + m;
                v[m] = (vy && xx >= 0 && xx < WW) ? xp[yy * WW + xx] : 0.f;
            }
        }
#pragma unroll
        for (int kx = 0; kx < KK; kx++) {
            float wv = wp[ky * KK + kx];
#pragma unroll
            for (int i = 0; i < 4; i++) acc[i] += v[i + kx] * wv;
        }
    }
    float4 o4 = make_float4(acc[0], acc[1], acc[2], acc[3]);
    *reinterpret_cast<float4*>(y + (long)idx * 4) = o4;
}

// ---------------- pointwise GEMM: Y[b,oc,p] = sum_c W[oc,c]*X[b,c,p] + bias ----------------
// tile: 128 px x 64 oc, 256 threads, 8px x 4oc micro-tile, float4 LDS
__global__ void pw_gemm_kernel(const float* __restrict__ X,
                               const float* __restrict__ W,
                               const float* __restrict__ bias,
                               float* __restrict__ Y,
                               int C, int OC,
                               long xbs, long ybs, long wbs,
                               int relu, float* __restrict__ msum)
{
    __shared__ float Xs[16][128];
    __shared__ float Ws[16][64];

    const int P = PP;
    int b = blockIdx.z;
    const float* Xb = X + (long)b * xbs;
    const float* Wp = W + (long)b * wbs;

    int p0  = blockIdx.x * 128;
    int oc0 = blockIdx.y * 64;
    int tx = threadIdx.x, ty = threadIdx.y;
    int t = ty * 16 + tx;

    float acc[4][8] = {};

    for (int c0 = 0; c0 < C; c0 += 16) {
        // Xs: 512 float4
#pragma unroll
        for (int i = t; i < 512; i += 256) {
            int cc = i >> 5, q = i & 31;
            reinterpret_cast<float4*>(&Xs[cc][0])[q] =
                reinterpret_cast<const float4*>(Xb + (long)(c0 + cc) * P + p0)[q];
        }
        // Ws: 1024 floats, consecutive t -> consecutive cc (coalesced per oc row)
#pragma unroll
        for (int i = t; i < 1024; i += 256) {
            int cc = i & 15, oo = i >> 4;
            int oc = oc0 + oo;
            Ws[cc][oo] = (oc < OC) ? Wp[(long)oc * C + c0 + cc] : 0.f;
        }
        __syncthreads();
#pragma unroll
        for (int cc = 0; cc < 16; cc++) {
            float4 x0 = *reinterpret_cast<const float4*>(&Xs[cc][tx * 8]);
            float4 x1 = *reinterpret_cast<const float4*>(&Xs[cc][tx * 8 + 4]);
            float4 wv = *reinterpret_cast<const float4*>(&Ws[cc][ty * 4]);
            float xv[8] = {x0.x, x0.y, x0.z, x0.w, x1.x, x1.y, x1.z, x1.w};
            float wa[4] = {wv.x, wv.y, wv.z, wv.w};
#pragma unroll
            for (int j = 0; j < 4; j++)
#pragma unroll
                for (int i = 0; i < 8; i++)
                    acc[j][i] += xv[i] * wa[j];
        }
        __syncthreads();
    }

    if (msum == nullptr) {
        float* Yb = Y + (long)b * ybs;
#pragma unroll
        for (int j = 0; j < 4; j++) {
            int oc = oc0 + ty * 4 + j;
            if (oc < OC) {
                float bb = bias[oc];
                float v[8];
#pragma unroll
                for (int i = 0; i < 8; i++) {
                    v[i] = acc[j][i] + bb;
                    if (relu) v[i] = fmaxf(v[i], 0.f);
                }
                float* yp = Yb + (long)oc * P + p0 + tx * 8;
                *reinterpret_cast<float4*>(yp)     = make_float4(v[0], v[1], v[2], v[3]);
                *reinterpret_cast<float4*>(yp + 4) = make_float4(v[4], v[5], v[6], v[7]);
            }
        }
    } else {
        // mean mode (OC==64): relu then partial sum over the 128 px of this tile
        __syncthreads();
        float* red = &Xs[0][0];     // reuse smem: [64 oc][16 tx]
#pragma unroll
        for (int j = 0; j < 4; j++) {
            float bb = bias[oc0 + ty * 4 + j];
            float s = 0.f;
#pragma unroll
            for (int i = 0; i < 8; i++) s += fmaxf(acc[j][i] + bb, 0.f);
            red[(ty * 4 + j) * 16 + tx] = s;
        }
        __syncthreads();
        if (t < 64) {
            float s = 0.f;
#pragma unroll
            for (int i = 0; i < 16; i++) s += red[t * 16 + i];
            msum[((long)b * 64 + t) * gridDim.x + blockIdx.x] = s;
        }
    }
}

// ---------------- finish mean: att[b,o] = sum(partials)/PP ----------------
__global__ void mean_finish_kernel(const float* __restrict__ msum, float* __restrict__ att)
{
    int o = blockIdx.x, b = blockIdx.y;
    const float* p = msum + ((long)b * 64 + o) * PTILES;
    float s = 0.f;
    for (int i = threadIdx.x; i < PTILES; i += 32) s += p[i];
#pragma unroll
    for (int off = 16; off > 0; off >>= 1) s += __shfl_xor_sync(0xffffffff, s, off);
    if (threadIdx.x == 0) att[b * 64 + o] = s / (float)PP;
}

// ---------------- modulated deformable conv ----------------
template <int KK>
__global__ void mdcn_kernel(const float* __restrict__ xin,
                            const float* __restrict__ om,
                            const float* __restrict__ w,
                            const float* __restrict__ bias,
                            float* __restrict__ out,
                            int branch)
{
    constexpr int K  = KK * KK;
    constexpr int CK = INC * K;
    __shared__ float Ws[CK][64];

    int tid = threadIdx.x;
    for (int i = tid; i < CK * 64; i += blockDim.x) {
        int ck = i >> 6, o = i & 63;
        Ws[ck][o] = w[o * CK + ck];
    }
    __syncthreads();

    int p = blockIdx.x * blockDim.x + tid;
    int b = blockIdx.y;
    if (p >= PP) return;
    int h  = p / WW;
    int wx = p - h * WW;
    const int pad = KK / 2;

    const float* omb = om + (long)b * (3 * CK) * PP;
    const float* xb  = xin + (long)b * INC * PP;

    float acc[64];
#pragma unroll
    for (int o = 0; o < 64; o++) acc[o] = 0.f;

    for (int c = 0; c < INC; c++) {
        const float* xc = xb + c * PP;
#pragma unroll
        for (int kk = 0; kk < K; kk++) {
            int ck = c * K + kk;
            float oy   = omb[(long)(2 * ck + 0) * PP + p];
            float ox   = omb[(long)(2 * ck + 1) * PP + p];
            float mraw = omb[(long)(2 * CK + ck) * PP + p];
            float m = 1.f / (1.f + __expf(-mraw));

            float py = oy + (float)(kk / KK) + (float)h - (float)pad;
            float px = ox + (float)(kk % KK) + (float)wx - (float)pad;
            float fy0 = floorf(py), fx0 = floorf(px);
            float wy = py - fy0, wxx = px - fx0;
            int iy0 = (int)fy0, ix0 = (int)fx0;
            int iy1 = iy0 + 1, ix1 = ix0 + 1;

            bool vy0 = (iy0 >= 0) & (iy0 < HH);
            bool vy1 = (iy1 >= 0) & (iy1 < HH);
            bool vx0 = (ix0 >= 0) & (ix0 < WW);
            bool vx1 = (ix1 >= 0) & (ix1 < WW);
            int cy0 = min(max(iy0, 0), HH - 1);
            int cy1 = min(max(iy1, 0), HH - 1);
            int cx0 = min(max(ix0, 0), WW - 1);
            int cx1 = min(max(ix1, 0), WW - 1);

            float v00 = (vy0 & vx0) ? xc[cy0 * WW + cx0] : 0.f;
            float v01 = (vy0 & vx1) ? xc[cy0 * WW + cx1] : 0.f;
            float v10 = (vy1 & vx0) ? xc[cy1 * WW + cx0] : 0.f;
            float v11 = (vy1 & vx1) ? xc[cy1 * WW + cx1] : 0.f;

            float s = (v00 * (1.f - wy) * (1.f - wxx) +
                       v01 * (1.f - wy) * wxx +
                       v10 * wy * (1.f - wxx) +
                       v11 * wy * wxx) * m;

            const float4* wr = reinterpret_cast<const float4*>(&Ws[ck][0]);
#pragma unroll
            for (int j = 0; j < 16; j++) {
                float4 w4 = wr[j];
                acc[4 * j + 0] += s * w4.x;
                acc[4 * j + 1] += s * w4.y;
                acc[4 * j + 2] += s * w4.z;
                acc[4 * j + 3] += s * w4.w;
            }
        }
    }

    float* ob = out + ((long)(b * 3 + branch) * 64) * PP + p;
#pragma unroll
    for (int o = 0; o < 64; o++)
        ob[(long)o * PP] = fmaxf(acc[o] + bias[o], 0.f);
}

// ---------------- tiny head: fc -> relu -> fcs -> atts; fold atts into conv_w ----------------
__global__ void head_kernel(const float* __restrict__ att,
                            const float* __restrict__ fc_w, const float* __restrict__ fc_b,
                            const float* __restrict__ fw0, const float* __restrict__ fb0,
                            const float* __restrict__ fw1, const float* __restrict__ fb1,
                            const float* __restrict__ fw2, const float* __restrict__ fb2,
                            const float* __restrict__ conv_w,
                            float* __restrict__ Wb, float* __restrict__ atts)
{
    __shared__ float a2[BN][32];
    int t = threadIdx.x;
    if (t < BN * 32) {
        int b = t >> 5, o = t & 31;
        float s = fc_b[o];
        for (int c = 0; c < 64; c++) s += fc_w[o * 64 + c] * att[b * 64 + c];
        a2[b][o] = fmaxf(s, 0.f);
    }
    __syncthreads();
    __shared__ float as[BN][192];
    for (int idx = t; idx < BN * 192; idx += blockDim.x) {
        int b = idx / 192, r = idx % 192;
        int i = r / 64, o = r % 64;
        const float* fw = (i == 0) ? fw0 : ((i == 1) ? fw1 : fw2);
        const float* fb = (i == 0) ? fb0 : ((i == 1) ? fb1 : fb2);
        float s = fb[o];
        for (int c = 0; c < 32; c++) s += fw[o * 32 + c] * a2[b][c];
        as[b][r] = s;
        atts[idx] = s;
    }
    __syncthreads();
    for (int idx = t; idx < BN * 64 * 192; idx += blockDim.x) {
        int b  = idx / (64 * 192);
        int r  = idx % (64 * 192);
        int o  = r / 192;
        int tc = r % 192;
        Wb[idx] = conv_w[o * 192 + tc] * as[b][tc];
    }
}

// ---------------- launch ----------------
extern "C" void kernel_launch(void* const* d_in, const int* in_sizes, int n_in,
                              void* d_out, int out_size)
{
    (void)in_sizes; (void)n_in; (void)out_size;
    const float* fea    = (const float*)d_in[0];
    const float* inputs = (const float*)d_in[1];
    const float* attn_w = (const float*)d_in[20];
    const float* attn_b = (const float*)d_in[21];
    const float* fc_w   = (const float*)d_in[22];
    const float* fc_b   = (const float*)d_in[23];
    const float* conv_w = (const float*)d_in[30];
    const float* conv_b = (const float*)d_in[31];

    float *dw, *om, *stack, *attp, *att, *atts, *Wb;
    cudaGetSymbolAddress((void**)&dw, g_dw);
    cudaGetSymbolAddress((void**)&om, g_om);
    cudaGetSymbolAddress((void**)&stack, g_stack);
    cudaGetSymbolAddress((void**)&attp, g_attp);
    cudaGetSymbolAddress((void**)&att, g_att);
    cudaGetSymbolAddress((void**)&atts, g_atts);
    cudaGetSymbolAddress((void**)&Wb, g_Wb);

    dim3 gthr(16, 16);

    for (int i = 0; i < 3; i++) {
        const float* dww  = (const float*)d_in[2 + 6 * i];
        const float* dwb  = (const float*)d_in[3 + 6 * i];
        const float* pww  = (const float*)d_in[4 + 6 * i];
        const float* pwb  = (const float*)d_in[5 + 6 * i];
        const float* dcnw = (const float*)d_in[6 + 6 * i];
        const float* dcnb = (const float*)d_in[7 + 6 * i];
        int k  = 2 * i + 1;
        int oc = INC * 3 * k * k;   // 21, 189, 525

        int total4 = BN * CF * PP / 4;
        int blocks = (total4 + 255) / 256;
        if (i == 0) dw_conv_kernel<1><<<blocks, 256>>>(fea, dww, dwb, dw);
        if (i == 1) dw_conv_kernel<3><<<blocks, 256>>>(fea, dww, dwb, dw);
        if (i == 2) dw_conv_kernel<5><<<blocks, 256>>>(fea, dww, dwb, dw);

        dim3 ggrid(PTILES, (oc + 63) / 64, BN);
        pw_gemm_kernel<<<ggrid, gthr>>>(dw, pww, pwb, om,
                                        64, oc,
                                        (long)64 * PP, (long)oc * PP, 0, 0, nullptr);

        dim3 mgrid(PP / 128, BN);
        if (i == 0) mdcn_kernel<1><<<mgrid, 128>>>(inputs, om, dcnw, dcnb, stack, i);
        if (i == 1) mdcn_kernel<3><<<mgrid, 128>>>(inputs, om, dcnw, dcnb, stack, i);
        if (i == 2) mdcn_kernel<5><<<mgrid, 128>>>(inputs, om, dcnw, dcnb, stack, i);
    }

    // attention: relu(pw(stack, attn_w)) -> mean (fused partial sums)
    dim3 agrid(PTILES, 1, BN);
    pw_gemm_kernel<<<agrid, gthr>>>(stack, attn_w, attn_b, nullptr,
                                    192, 64,
                                    (long)192 * PP, 0, 0, 1, attp);
    dim3 rgrid(64, BN);
    mean_finish_kernel<<<rgrid, 32>>>(attp, att);

    head_kernel<<<1, 256>>>(att, fc_w, fc_b,
                            (const float*)d_in[24], (const float*)d_in[25],
                            (const float*)d_in[26], (const float*)d_in[27],
                            (const float*)d_in[28], (const float*)d_in[29],
                            conv_w, Wb, atts);

    // final: relu(pw(stack, Wb)) with atts folded into per-batch weights
    pw_gemm_kernel<<<agrid, gthr>>>(stack, Wb, conv_b, (float*)d_out,
                                    192, 64,
                                    (long)192 * PP, (long)64 * PP, (long)64 * 192, 1, nullptr);
}

// round 3
// speedup vs baseline: 1.1437x; 1.1437x over previous
#include <cuda_runtime.h>
#include <cuda_bf16.h>
#include <math.h>

#define BN 4
#define HH 192
#define WW 192
#define PP (HH*WW)           // 36864
#define CF 64
#define ONC 64
#define INC 7
#define PTILES (PP/128)      // 288

// ---------------- scratch (device globals; no runtime allocation) ----------------
__device__ float g_dw[BN * CF * PP];            // depthwise output
__device__ float g_om[BN * 525 * PP];           // offset/mask (max k=5)
__device__ float g_stack[BN * 3 * ONC * PP];    // stacked branch outputs
__device__ float g_attp[BN * ONC * PTILES];     // attn partial sums
__device__ float g_att[BN * ONC];
__device__ float g_atts[BN * 3 * ONC];
__device__ float g_Wb[BN * ONC * 3 * ONC];      // per-batch scaled conv_w

// ---------------- depthwise conv (k = 1,3,5, SAME padding), 4 px / thread ----------------
template <int KK>
__global__ void dw_conv_kernel(const float* __restrict__ x,
                               const float* __restrict__ w,
                               const float* __restrict__ bias,
                               float* __restrict__ y)
{
    const int P4 = PP / 4;
    int idx = blockIdx.x * blockDim.x + threadIdx.x;
    if (idx >= BN * CF * P4) return;
    int p4 = idx % P4;
    int c  = (idx / P4) % CF;
    int b  = idx / (CF * P4);
    int p  = p4 * 4;
    int h  = p / WW;
    int x0 = p - h * WW;                 // WW divisible by 4: 4 px same row
    const int pad = KK / 2;
    const float* xp = x + ((long)(b * CF + c)) * PP;
    const float* wp = w + c * KK * KK;

    float acc[4];
    float bb = bias[c];
#pragma unroll
    for (int i = 0; i < 4; i++) acc[i] = bb;

    bool inter = (h >= pad) && (h < HH - pad) && (x0 >= pad) && (x0 + 3 + pad < WW);

#pragma unroll
    for (int ky = 0; ky < KK; ky++) {
        int yy = h + ky - pad;
        const float* r = xp + yy * WW + x0 - pad;
        float v[KK + 3];
        if (inter) {
#pragma unroll
            for (int m = 0; m < KK + 3; m++) v[m] = r[m];
        } else {
            bool vy = (yy >= 0) && (yy < HH);
#pragma unroll
            for (int m = 0; m < KK + 3; m++) {
                int xx = x0 - pad + m;
                v[m] = (vy && xx >= 0 && xx < WW) ? xp[yy * WW + xx] : 0.f;
            }
        }
#pragma unroll
        for (int kx = 0; kx < KK; kx++) {
            float wv = wp[ky * KK + kx];
#pragma unroll
            for (int i = 0; i < 4; i++) acc[i] += v[i + kx] * wv;
        }
    }
    float4 o4 = make_float4(acc[0], acc[1], acc[2], acc[3]);
    *reinterpret_cast<float4*>(y + (long)idx * 4) = o4;
}

// ---------------- pointwise GEMM: Y[b,oc,p] = sum_c W[oc,c]*X[b,c,p] + bias ----------------
// tile: 128 px x 64 oc, 256 threads, 8px x 4oc micro-tile, conflict-free float4 LDS
__global__ void pw_gemm_kernel(const float* __restrict__ X,
                               const float* __restrict__ W,
                               const float* __restrict__ bias,
                               float* __restrict__ Y,
                               int C, int OC,
                               long xbs, long ybs, long wbs,
                               int relu, float* __restrict__ msum)
{
    __shared__ float Xs[16 * 128];
    __shared__ float Ws[16 * 64];

    const int P = PP;
    int b = blockIdx.z;
    const float* Xb = X + (long)b * xbs;
    const float* Wp = W + (long)b * wbs;

    int p0  = blockIdx.x * 128;
    int oc0 = blockIdx.y * 64;
    int tx = threadIdx.x, ty = threadIdx.y;
    int t = ty * 16 + tx;

    float4* Xs4 = reinterpret_cast<float4*>(Xs);
    float4* Ws4 = reinterpret_cast<float4*>(Ws);

    float acc[4][8] = {};

    for (int c0 = 0; c0 < C; c0 += 16) {
        // Xs: 512 float4, lane-major over px -> STS conflict-free, LDG coalesced
#pragma unroll
        for (int i = t; i < 512; i += 256) {
            int cc = i >> 5, q = i & 31;
            Xs4[cc * 32 + q] =
                reinterpret_cast<const float4*>(Xb + (long)(c0 + cc) * P + p0)[q];
        }
        // Ws: lane-major over oo -> STS conflict-free
#pragma unroll
        for (int i = t; i < 1024; i += 256) {
            int oo = i & 63, cc = i >> 6;
            int oc = oc0 + oo;
            Ws[cc * 64 + oo] = (oc < OC) ? Wp[(long)oc * C + c0 + cc] : 0.f;
        }
        __syncthreads();
#pragma unroll
        for (int cc = 0; cc < 16; cc++) {
            float4 xa = Xs4[cc * 32 + tx];          // px tx*4..tx*4+3   (16B lane stride)
            float4 xb2 = Xs4[cc * 32 + 16 + tx];    // px tx*4+64..+67
            float4 wv = Ws4[cc * 16 + ty];          // broadcast within half-warp
            float xv[8] = {xa.x, xa.y, xa.z, xa.w, xb2.x, xb2.y, xb2.z, xb2.w};
            float wa[4] = {wv.x, wv.y, wv.z, wv.w};
#pragma unroll
            for (int j = 0; j < 4; j++)
#pragma unroll
                for (int i = 0; i < 8; i++)
                    acc[j][i] += xv[i] * wa[j];
        }
        __syncthreads();
    }

    if (msum == nullptr) {
        float* Yb = Y + (long)b * ybs;
#pragma unroll
        for (int j = 0; j < 4; j++) {
            int oc = oc0 + ty * 4 + j;
            if (oc < OC) {
                float bb = bias[oc];
                float v[8];
#pragma unroll
                for (int i = 0; i < 8; i++) {
                    v[i] = acc[j][i] + bb;
                    if (relu) v[i] = fmaxf(v[i], 0.f);
                }
                float* yp = Yb + (long)oc * P + p0 + tx * 4;
                *reinterpret_cast<float4*>(yp)      = make_float4(v[0], v[1], v[2], v[3]);
                *reinterpret_cast<float4*>(yp + 64) = make_float4(v[4], v[5], v[6], v[7]);
            }
        }
    } else {
        // mean mode (OC==64): relu then partial sum over the 128 px of this tile
        __syncthreads();
        float* red = Xs;     // reuse smem: [64 oc][16 tx]
#pragma unroll
        for (int j = 0; j < 4; j++) {
            float bb = bias[oc0 + ty * 4 + j];
            float s = 0.f;
#pragma unroll
            for (int i = 0; i < 8; i++) s += fmaxf(acc[j][i] + bb, 0.f);
            red[(ty * 4 + j) * 16 + tx] = s;
        }
        __syncthreads();
        if (t < 64) {
            float s = 0.f;
#pragma unroll
            for (int i = 0; i < 16; i++) s += red[t * 16 + i];
            msum[((long)b * 64 + t) * gridDim.x + blockIdx.x] = s;
        }
    }
}

// ---------------- finish mean: att[b,o] = sum(partials)/PP ----------------
__global__ void mean_finish_kernel(const float* __restrict__ msum, float* __restrict__ att)
{
    int o = blockIdx.x, b = blockIdx.y;
    const float* p = msum + ((long)b * 64 + o) * PTILES;
    float s = 0.f;
    for (int i = threadIdx.x; i < PTILES; i += 32) s += p[i];
#pragma unroll
    for (int off = 16; off > 0; off >>= 1) s += __shfl_xor_sync(0xffffffff, s, off);
    if (threadIdx.x == 0) att[b * 64 + o] = s / (float)PP;
}

// ---------------- modulated deformable conv ----------------
template <int KK>
__global__ void mdcn_kernel(const float* __restrict__ xin,
                            const float* __restrict__ om,
                            const float* __restrict__ w,
                            const float* __restrict__ bias,
                            float* __restrict__ out,
                            int branch)
{
    constexpr int K  = KK * KK;
    constexpr int CK = INC * K;
    __shared__ float Ws[CK][64];

    int tid = threadIdx.x;
    for (int i = tid; i < CK * 64; i += blockDim.x) {
        int ck = i >> 6, o = i & 63;
        Ws[ck][o] = w[o * CK + ck];
    }
    __syncthreads();

    int p = blockIdx.x * blockDim.x + tid;
    int b = blockIdx.y;
    if (p >= PP) return;
    int h  = p / WW;
    int wx = p - h * WW;
    const int pad = KK / 2;

    const float* omb = om + (long)b * (3 * CK) * PP;
    const float* xb  = xin + (long)b * INC * PP;

    float acc[64];
#pragma unroll
    for (int o = 0; o < 64; o++) acc[o] = 0.f;

    for (int c = 0; c < INC; c++) {
        const float* xc = xb + c * PP;
#pragma unroll
        for (int kk = 0; kk < K; kk++) {
            int ck = c * K + kk;
            float oy   = omb[(long)(2 * ck + 0) * PP + p];
            float ox   = omb[(long)(2 * ck + 1) * PP + p];
            float mraw = omb[(long)(2 * CK + ck) * PP + p];
            float m = 1.f / (1.f + __expf(-mraw));

            float py = oy + (float)(kk / KK) + (float)h - (float)pad;
            float px = ox + (float)(kk % KK) + (float)wx - (float)pad;
            float fy0 = floorf(py), fx0 = floorf(px);
            float wy = py - fy0, wxx = px - fx0;
            int iy0 = (int)fy0, ix0 = (int)fx0;
            int iy1 = iy0 + 1, ix1 = ix0 + 1;

            bool vy0 = (iy0 >= 0) & (iy0 < HH);
            bool vy1 = (iy1 >= 0) & (iy1 < HH);
            bool vx0 = (ix0 >= 0) & (ix0 < WW);
            bool vx1 = (ix1 >= 0) & (ix1 < WW);
            int cy0 = min(max(iy0, 0), HH - 1);
            int cy1 = min(max(iy1, 0), HH - 1);
            int cx0 = min(max(ix0, 0), WW - 1);
            int cx1 = min(max(ix1, 0), WW - 1);

            float v00 = (vy0 & vx0) ? xc[cy0 * WW + cx0] : 0.f;
            float v01 = (vy0 & vx1) ? xc[cy0 * WW + cx1] : 0.f;
            float v10 = (vy1 & vx0) ? xc[cy1 * WW + cx0] : 0.f;
            float v11 = (vy1 & vx1) ? xc[cy1 * WW + cx1] : 0.f;

            float s = (v00 * (1.f - wy) * (1.f - wxx) +
                       v01 * (1.f - wy) * wxx +
                       v10 * wy * (1.f - wxx) +
                       v11 * wy * wxx) * m;

            const float4* wr = reinterpret_cast<const float4*>(&Ws[ck][0]);
#pragma unroll
            for (int j = 0; j < 16; j++) {
                float4 w4 = wr[j];
                acc[4 * j + 0] += s * w4.x;
                acc[4 * j + 1] += s * w4.y;
                acc[4 * j + 2] += s * w4.z;
                acc[4 * j + 3] += s * w4.w;
            }
        }
    }

    float* ob = out + ((long)(b * 3 + branch) * 64) * PP + p;
#pragma unroll
    for (int o = 0; o < 64; o++)
        ob[(long)o * PP] = fmaxf(acc[o] + bias[o], 0.f);
}

// ---------------- tiny head: fc -> relu -> fcs -> atts; fold atts into conv_w ----------------
__global__ void head_kernel(const float* __restrict__ att,
                            const float* __restrict__ fc_w, const float* __restrict__ fc_b,
                            const float* __restrict__ fw0, const float* __restrict__ fb0,
                            const float* __restrict__ fw1, const float* __restrict__ fb1,
                            const float* __restrict__ fw2, const float* __restrict__ fb2,
                            const float* __restrict__ conv_w,
                            float* __restrict__ Wb, float* __restrict__ atts)
{
    __shared__ float a2[BN][32];
    int t = threadIdx.x;
    if (t < BN * 32) {
        int b = t >> 5, o = t & 31;
        float s = fc_b[o];
        for (int c = 0; c < 64; c++) s += fc_w[o * 64 + c] * att[b * 64 + c];
        a2[b][o] = fmaxf(s, 0.f);
    }
    __syncthreads();
    __shared__ float as[BN][192];
    for (int idx = t; idx < BN * 192; idx += blockDim.x) {
        int b = idx / 192, r = idx % 192;
        int i = r / 64, o = r % 64;
        const float* fw = (i == 0) ? fw0 : ((i == 1) ? fw1 : fw2);
        const float* fb = (i == 0) ? fb0 : ((i == 1) ? fb1 : fb2);
        float s = fb[o];
        for (int c = 0; c < 32; c++) s += fw[o * 32 + c] * a2[b][c];
        as[b][r] = s;
        atts[idx] = s;
    }
    __syncthreads();
    for (int idx = t; idx < BN * 64 * 192; idx += blockDim.x) {
        int b  = idx / (64 * 192);
        int r  = idx % (64 * 192);
        int o  = r / 192;
        int tc = r % 192;
        Wb[idx] = conv_w[o * 192 + tc] * as[b][tc];
    }
}

// ---------------- launch ----------------
extern "C" void kernel_launch(void* const* d_in, const int* in_sizes, int n_in,
                              void* d_out, int out_size)
{
    (void)in_sizes; (void)n_in; (void)out_size;
    const float* fea    = (const float*)d_in[0];
    const float* inputs = (const float*)d_in[1];
    const float* attn_w = (const float*)d_in[20];
    const float* attn_b = (const float*)d_in[21];
    const float* fc_w   = (const float*)d_in[22];
    const float* fc_b   = (const float*)d_in[23];
    const float* conv_w = (const float*)d_in[30];
    const float* conv_b = (const float*)d_in[31];

    float *dw, *om, *stack, *attp, *att, *atts, *Wb;
    cudaGetSymbolAddress((void**)&dw, g_dw);
    cudaGetSymbolAddress((void**)&om, g_om);
    cudaGetSymbolAddress((void**)&stack, g_stack);
    cudaGetSymbolAddress((void**)&attp, g_attp);
    cudaGetSymbolAddress((void**)&att, g_att);
    cudaGetSymbolAddress((void**)&atts, g_atts);
    cudaGetSymbolAddress((void**)&Wb, g_Wb);

    dim3 gthr(16, 16);

    for (int i = 0; i < 3; i++) {
        const float* dww  = (const float*)d_in[2 + 6 * i];
        const float* dwb  = (const float*)d_in[3 + 6 * i];
        const float* pww  = (const float*)d_in[4 + 6 * i];
        const float* pwb  = (const float*)d_in[5 + 6 * i];
        const float* dcnw = (const float*)d_in[6 + 6 * i];
        const float* dcnb = (const float*)d_in[7 + 6 * i];
        int k  = 2 * i + 1;
        int oc = INC * 3 * k * k;   // 21, 189, 525

        int total4 = BN * CF * PP / 4;
        int blocks = (total4 + 255) / 256;
        if (i == 0) dw_conv_kernel<1><<<blocks, 256>>>(fea, dww, dwb, dw);
        if (i == 1) dw_conv_kernel<3><<<blocks, 256>>>(fea, dww, dwb, dw);
        if (i == 2) dw_conv_kernel<5><<<blocks, 256>>>(fea, dww, dwb, dw);

        dim3 ggrid(PTILES, (oc + 63) / 64, BN);
        pw_gemm_kernel<<<ggrid, gthr>>>(dw, pww, pwb, om,
                                        64, oc,
                                        (long)64 * PP, (long)oc * PP, 0, 0, nullptr);

        dim3 mgrid(PP / 128, BN);
        if (i == 0) mdcn_kernel<1><<<mgrid, 128>>>(inputs, om, dcnw, dcnb, stack, i);
        if (i == 1) mdcn_kernel<3><<<mgrid, 128>>>(inputs, om, dcnw, dcnb, stack, i);
        if (i == 2) mdcn_kernel<5><<<mgrid, 128>>>(inputs, om, dcnw, dcnb, stack, i);
    }

    // attention: relu(pw(stack, attn_w)) -> mean (fused partial sums)
    dim3 agrid(PTILES, 1, BN);
    pw_gemm_kernel<<<agrid, gthr>>>(stack, attn_w, attn_b, nullptr,
                                    192, 64,
                                    (long)192 * PP, 0, 0, 1, attp);
    dim3 rgrid(64, BN);
    mean_finish_kernel<<<rgrid, 32>>>(attp, att);

    head_kernel<<<1, 256>>>(att, fc_w, fc_b,
                            (const float*)d_in[24], (const float*)d_in[25],
                            (const float*)d_in[26], (const float*)d_in[27],
                            (const float*)d_in[28], (const float*)d_in[29],
                            conv_w, Wb, atts);

    // final: relu(pw(stack, Wb)) with atts folded into per-batch weights
    pw_gemm_kernel<<<agrid, gthr>>>(stack, Wb, conv_b, (float*)d_out,
                                    192, 64,
                                    (long)192 * PP, (long)64 * PP, (long)64 * 192, 1, nullptr);
}